// round 10
// baseline (speedup 1.0000x reference)
#include <cuda_runtime.h>
#include <cuda_bf16.h>
#include <cstdint>
#include <cstddef>

#define Nn   100000
#define Ee   256000
#define EMB  300
#define EMB2 600
#define LAYERS 5

#define KP1 320
#define KP2 640
#define NCH1 5
#define NCH2 10
#define NPAD1 640   // 5 n-tiles of 128
#define NPAD2 384   // 3 n-tiles of 128

// ---------------- device scratch ----------------
__device__ __align__(128) float  g_hbufA[(size_t)Nn * EMB];
__device__ __align__(128) float  g_hbufB[(size_t)Nn * EMB];
__device__ __align__(128) float  g_agg  [(size_t)Nn * EMB];
__device__ __align__(128) float  g_z1   [(size_t)Nn * EMB2];
__device__ __align__(128) float  g_z2   [(size_t)Nn * EMB];
__device__ __align__(128) __nv_bfloat16 g_Ahi[(size_t)Nn * KP2];
__device__ __align__(128) __nv_bfloat16 g_Alo[(size_t)Nn * KP2];
__device__ __align__(128) __nv_bfloat16 g_Bhi[262144];
__device__ __align__(128) __nv_bfloat16 g_Blo[262144];
__device__ __align__(16) float g_etab [9 * EMB];
__device__ double g_sum  [EMB2];
__device__ double g_sq   [EMB2];
__device__ float  g_sc1  [EMB2];
__device__ float  g_sh1  [EMB2];
__device__ float  g_sc2  [EMB];
__device__ float  g_sh2  [EMB];

// ---------------- PTX helpers ----------------
__device__ __forceinline__ uint32_t smem_u32(const void* p) {
    uint32_t a;
    asm("{ .reg .u64 t; cvta.to.shared.u64 t, %1; cvt.u32.u64 %0, t; }" : "=r"(a) : "l"(p));
    return a;
}
__device__ __forceinline__ void cp_async16(uint32_t dst, const void* src) {
    asm volatile("cp.async.cg.shared.global [%0], [%1], 16;" :: "r"(dst), "l"(src));
}
// src-size 0 zero-fills the 16B destination — keeps stats exact for padded rows
__device__ __forceinline__ void cp_async16p(uint32_t dst, const void* src, bool valid) {
    int sz = valid ? 16 : 0;
    asm volatile("cp.async.cg.shared.global [%0], [%1], 16, %2;" :: "r"(dst), "l"(src), "r"(sz));
}
__device__ __forceinline__ void cp_commit() { asm volatile("cp.async.commit_group;"); }
__device__ __forceinline__ uint32_t swz(uint32_t b) { return b ^ ((b >> 3) & 0x70); }

__device__ __forceinline__ void ldsm_x4(uint32_t (&r)[4], uint32_t addr) {
    asm volatile("ldmatrix.sync.aligned.m8n8.x4.shared.b16 {%0,%1,%2,%3}, [%4];"
        : "=r"(r[0]), "=r"(r[1]), "=r"(r[2]), "=r"(r[3]) : "r"(addr));
}
__device__ __forceinline__ void mma16816(float (&d)[4], const uint32_t (&a)[4],
                                         uint32_t b0, uint32_t b1) {
    asm volatile("mma.sync.aligned.m16n8k16.row.col.f32.bf16.bf16.f32 "
        "{%0,%1,%2,%3}, {%4,%5,%6,%7}, {%8,%9}, {%0,%1,%2,%3};"
        : "+f"(d[0]), "+f"(d[1]), "+f"(d[2]), "+f"(d[3])
        : "r"(a[0]), "r"(a[1]), "r"(a[2]), "r"(a[3]), "r"(b0), "r"(b1));
}
__device__ __forceinline__ void red_add_v4(float* addr, float a, float b, float c, float d) {
    asm volatile("red.global.add.v4.f32 [%0], {%1,%2,%3,%4};"
        :: "l"(addr), "f"(a), "f"(b), "f"(c), "f"(d) : "memory");
}

// ---------------- elementwise / prep kernels ----------------
__global__ void agg_init(const float* __restrict__ h, const float* __restrict__ eps, int l) {
    int i = blockIdx.x * blockDim.x + threadIdx.x;
    if (i < Nn * EMB) g_agg[i] = (1.0f + __ldg(eps + l)) * h[i];
}

// prep1: split W1 -> Bhi/Blo (0..639), etab (640..648), zero stats600 (649)
__global__ void prep1(const float* __restrict__ W1, const float* __restrict__ Wb) {
    int b = blockIdx.x, t = threadIdx.x;
    if (b < NPAD1) {
        float v = (b < EMB2 && t < EMB) ? W1[(size_t)b * EMB + t] : 0.0f;
        __nv_bfloat16 h = __float2bfloat16_rn(v);
        g_Bhi[(size_t)b * KP1 + t] = h;
        g_Blo[(size_t)b * KP1 + t] = __float2bfloat16_rn(v - __bfloat162float(h));
    } else if (b < NPAD1 + 9) {
        int c = b - NPAD1;
        if (t < EMB) g_etab[c * EMB + t] = Wb[t * 9 + c / 3] + Wb[t * 9 + 6 + (c % 3)];
    } else {
        for (int i = t; i < EMB2; i += blockDim.x) { g_sum[i] = 0.0; g_sq[i] = 0.0; }
    }
}

// prep2: split W2 (0..383); block 384: BN1 finalize THEN (ordered) zero stats300
__global__ void prep2(const float* __restrict__ W2,
                      const float* __restrict__ gamma, const float* __restrict__ beta) {
    int b = blockIdx.x, t = threadIdx.x;
    if (b < NPAD2) {
        for (int c = t; c < KP2; c += blockDim.x) {
            float v = (b < EMB && c < EMB2) ? W2[(size_t)b * EMB2 + c] : 0.0f;
            __nv_bfloat16 h = __float2bfloat16_rn(v);
            g_Bhi[(size_t)b * KP2 + c] = h;
            g_Blo[(size_t)b * KP2 + c] = __float2bfloat16_rn(v - __bfloat162float(h));
        }
    } else {
        for (int i = t; i < EMB2; i += blockDim.x) {
            double m = g_sum[i] / (double)Nn;
            double v = g_sq[i] / (double)Nn - m * m;
            float rs = rsqrtf((float)v + 1e-5f);
            float a = gamma[i] * rs;
            g_sc1[i] = a;
            g_sh1[i] = beta[i] - a * (float)m;
        }
        __syncthreads();
        for (int i = t; i < EMB; i += blockDim.x) { g_sum[i] = 0.0; g_sq[i] = 0.0; }
    }
}

__global__ void bn_finalize2(const float* __restrict__ gamma, const float* __restrict__ beta) {
    int i = blockIdx.x * blockDim.x + threadIdx.x;
    if (i >= EMB) return;
    double m = g_sum[i] / (double)Nn;
    double v = g_sq[i] / (double)Nn - m * m;
    float rs = rsqrtf((float)v + 1e-5f);
    float a = gamma[i] * rs;
    g_sc2[i] = a;
    g_sh2[i] = beta[i] - a * (float)m;
}

__global__ void bn_apply_agg(const float* __restrict__ Z, float* __restrict__ outh,
                             const float* __restrict__ eps, int lnext, int relu, int wagg) {
    int i = blockIdx.x * blockDim.x + threadIdx.x;
    if (i >= Nn * EMB) return;
    int col = i % EMB;
    float v = fmaf(g_sc2[col], Z[i], g_sh2[col]);
    if (relu) v = fmaxf(v, 0.0f);
    outh[i] = v;
    if (wagg) g_agg[i] = (1.0f + __ldg(eps + lnext)) * v;
}

// ---------------- standalone A split: fp32 -> bf16 hi/lo, float4 vectorized ----------
template <int TRANSFORM, int K, int KP>
__global__ void __launch_bounds__(256)
split_A(const float* __restrict__ src) {
    const int qpr = KP / 4;
    int i = blockIdx.x * blockDim.x + threadIdx.x;
    if (i >= Nn * qpr) return;
    int row = i / qpr;
    int col = (i - row * qpr) * 4;
    float4 v = make_float4(0.f, 0.f, 0.f, 0.f);
    if (col < K) {
        v = *reinterpret_cast<const float4*>(src + (size_t)row * K + col);
        if (TRANSFORM) {
            float4 cs = *reinterpret_cast<const float4*>(g_sc1 + col);
            float4 ds = *reinterpret_cast<const float4*>(g_sh1 + col);
            v.x = fmaxf(fmaf(cs.x, v.x, ds.x), 0.f);
            v.y = fmaxf(fmaf(cs.y, v.y, ds.y), 0.f);
            v.z = fmaxf(fmaf(cs.z, v.z, ds.z), 0.f);
            v.w = fmaxf(fmaf(cs.w, v.w, ds.w), 0.f);
        }
    }
    __nv_bfloat162 H0 = __floats2bfloat162_rn(v.x, v.y);
    __nv_bfloat162 H1 = __floats2bfloat162_rn(v.z, v.w);
    __nv_bfloat162 L0 = __floats2bfloat162_rn(v.x - __low2float(H0), v.y - __high2float(H0));
    __nv_bfloat162 L1 = __floats2bfloat162_rn(v.z - __low2float(H1), v.w - __high2float(H1));
    uint2 hv = make_uint2(*reinterpret_cast<uint32_t*>(&H0), *reinterpret_cast<uint32_t*>(&H1));
    uint2 lv = make_uint2(*reinterpret_cast<uint32_t*>(&L0), *reinterpret_cast<uint32_t*>(&L1));
    *reinterpret_cast<uint2*>(g_Ahi + (size_t)row * KP + col) = hv;
    *reinterpret_cast<uint2*>(g_Alo + (size_t)row * KP + col) = lv;
}

// ---------------- edge scatter (unchanged from R9) ----------------
#define EDGES_PER_BLOCK 64
__global__ void __launch_bounds__(256)
edge_msg(const float* __restrict__ h, const int* __restrict__ ei,
         const int* __restrict__ ea) {
    __shared__ __align__(16) float s_et[9 * EMB];
    for (int i = threadIdx.x; i < 9 * EMB; i += blockDim.x) s_et[i] = g_etab[i];
    __syncthreads();

    int warp = threadIdx.x >> 5, lane = threadIdx.x & 31;
    int ebase = blockIdx.x * EDGES_PER_BLOCK + warp * (EDGES_PER_BLOCK / 8);

#pragma unroll
    for (int u = 0; u < EDGES_PER_BLOCK / 8; u++) {
        int e = ebase + u;
        if (e >= Ee) return;
        int src = __ldg(ei + e);
        int dst = __ldg(ei + Ee + e);
        int c   = __ldg(ea + 2 * e) * 3 + __ldg(ea + 2 * e + 1);

        const float4* hr = reinterpret_cast<const float4*>(h + (size_t)src * EMB);
        float*        ar = g_agg + (size_t)dst * EMB;
        const float4* er = reinterpret_cast<const float4*>(s_et + c * EMB);

#pragma unroll
        for (int it = 0; it < 3; it++) {
            int k = lane + it * 32;
            if (k < 75) {
                float4 hv = __ldg(hr + k);
                float4 ev = er[k];
                float a = fmaxf(hv.x + ev.x, 0.0f);
                float b = fmaxf(hv.y + ev.y, 0.0f);
                float cc = fmaxf(hv.z + ev.z, 0.0f);
                float d = fmaxf(hv.w + ev.w, 0.0f);
                if (a + b + cc + d > 0.0f)
                    red_add_v4(ar + k * 4, a, b, cc, d);
            }
        }
    }
}

// ---------------- lean split-bf16 GEMM: cp.async both operands, 2 CTAs/SM ----------
// C[M,NC] = Ah*Bh^T + Al*Bh^T + Ah*Bl^T via 3*nch virtual chunks (phase-derived ptrs).
// 3-stage cp.async pipeline; fused BN stats epilogue (padded rows are cp.async zero-filled).
__global__ void __launch_bounds__(256, 2)
gemm_lean(const __nv_bfloat16* __restrict__ Ahi, const __nv_bfloat16* __restrict__ Alo,
          const __nv_bfloat16* __restrict__ Bhi, const __nv_bfloat16* __restrict__ Blo,
          float* __restrict__ C, int M, int NC, int KP, int nch) {
    extern __shared__ __align__(1024) char smem[];
    uint32_t sb = smem_u32(smem);

    int tid = threadIdx.x;
    int wid = tid >> 5, lane = tid & 31;
    int wm = wid >> 2, wn = wid & 3;        // 2(M) x 4(N) warps
    int n0 = blockIdx.x * 128;              // n fastest -> A L2 reuse
    int m0 = blockIdx.y * 128;
    int niter = 3 * nch;

    int quad = lane >> 3, r = lane & 7;
    int arow_base = wm * 64 + (quad & 1) * 8 + r;
    int brow_base = wn * 32 + (quad & 1) * 8 + r;
    int kseg_add = quad >> 1;

    float acc[4][4][4];
#pragma unroll
    for (int mi = 0; mi < 4; mi++)
#pragma unroll
        for (int nt = 0; nt < 4; nt++)
#pragma unroll
            for (int q = 0; q < 4; q++) acc[mi][nt][q] = 0.0f;

    auto load_chunk = [&](int c, int buf) {
        int p = c / nch, kc = c - p * nch;
        const __nv_bfloat16* Ab = (p == 1) ? Alo : Ahi;
        const __nv_bfloat16* Bb = (p == 2) ? Blo : Bhi;
        size_t aoff = (size_t)m0 * KP + (size_t)kc * 64;
        size_t boff = (size_t)n0 * KP + (size_t)kc * 64;
        uint32_t sA = sb + buf * 32768;
        uint32_t sB = sA + 16384;
#pragma unroll
        for (int i = 0; i < 4; i++) {
            int seg = tid + i * 256;
            int row = seg >> 3, s = seg & 7;
            uint32_t so = swz(row * 128 + s * 16);
            cp_async16p(sA + so, Ab + aoff + (size_t)row * KP + s * 8, (m0 + row) < M);
            cp_async16(sB + so, Bb + boff + (size_t)row * KP + s * 8);
        }
        cp_commit();
    };

    load_chunk(0, 0);
    load_chunk(1, 1);

    for (int j = 0; j < niter; j++) {
        if (j + 2 < niter) asm volatile("cp.async.wait_group 1;" ::: "memory");
        else               asm volatile("cp.async.wait_group 0;" ::: "memory");
        __syncthreads();

        if (j + 2 < niter) load_chunk(j + 2, (j + 2) % 3);

        uint32_t sA = sb + (j % 3) * 32768;
        uint32_t sB = sA + 16384;
#pragma unroll
        for (int ks = 0; ks < 4; ks++) {
            int kseg = ks * 2 + kseg_add;
            uint32_t a[4][4];
#pragma unroll
            for (int mi = 0; mi < 4; mi++)
                ldsm_x4(a[mi], sA + swz((arow_base + mi * 16) * 128 + kseg * 16));
            uint32_t b[2][4];
#pragma unroll
            for (int nj = 0; nj < 2; nj++)
                ldsm_x4(b[nj], sB + swz((brow_base + nj * 16) * 128 + kseg * 16));
#pragma unroll
            for (int mi = 0; mi < 4; mi++)
#pragma unroll
                for (int nt = 0; nt < 4; nt++)
                    mma16816(acc[mi][nt], a[mi], b[nt >> 1][nt & 1], b[nt >> 1][(nt & 1) + 2]);
        }
        __syncthreads();
    }

    // ---- epilogue: C stores ----
    int rg = lane >> 2, cg = (lane & 3) * 2;
#pragma unroll
    for (int mi = 0; mi < 4; mi++) {
        int r0 = m0 + wm * 64 + mi * 16 + rg;
#pragma unroll
        for (int nt = 0; nt < 4; nt++) {
            int c0 = n0 + wn * 32 + nt * 8 + cg;
            if (c0 < NC) {
                if (r0 < M)
                    *reinterpret_cast<float2*>(C + (size_t)r0 * NC + c0) =
                        make_float2(acc[mi][nt][0], acc[mi][nt][1]);
                if (r0 + 8 < M)
                    *reinterpret_cast<float2*>(C + (size_t)(r0 + 8) * NC + c0) =
                        make_float2(acc[mi][nt][2], acc[mi][nt][3]);
            }
        }
    }

    // ---- epilogue: fused BN stats (padded rows zero-filled => contribute 0) ----
#pragma unroll
    for (int nt = 0; nt < 4; nt++) {
#pragma unroll
        for (int cp = 0; cp < 2; cp++) {
            float s = 0.f, q = 0.f;
#pragma unroll
            for (int mi = 0; mi < 4; mi++) {
                float v0 = acc[mi][nt][cp];
                float v1 = acc[mi][nt][cp + 2];
                s += v0 + v1;
                q += v0 * v0 + v1 * v1;
            }
#pragma unroll
            for (int off = 4; off <= 16; off <<= 1) {
                s += __shfl_xor_sync(0xFFFFFFFF, s, off);
                q += __shfl_xor_sync(0xFFFFFFFF, q, off);
            }
            if ((lane >> 2) == 0) {
                int c0 = n0 + wn * 32 + nt * 8 + (lane & 3) * 2 + cp;
                if (c0 < NC) {
                    atomicAdd(&g_sum[c0], (double)s);
                    atomicAdd(&g_sq[c0], (double)q);
                }
            }
        }
    }
}

// ---------------- launcher ----------------
extern "C" void kernel_launch(void* const* d_in, const int* in_sizes, int n_in,
                              void* d_out, int out_size) {
    const float* x    = (const float*)d_in[0];
    const float* Wb   = (const float*)d_in[1];
    const float* eps  = (const float*)d_in[2];
    const float* W1   = (const float*)d_in[3];
    const float* bn1g = (const float*)d_in[5];
    const float* bn1b = (const float*)d_in[6];
    const float* W2   = (const float*)d_in[7];
    const float* bng  = (const float*)d_in[9];
    const float* bnb  = (const float*)d_in[10];
    const int*   ei   = (const int*)d_in[11];
    const int*   ea   = (const int*)d_in[12];
    float* out = (float*)d_out;

    float *hA, *hB, *agg, *z1, *z2;
    __nv_bfloat16 *Ahi, *Alo, *Bhi, *Blo;
    cudaGetSymbolAddress((void**)&hA,  g_hbufA);
    cudaGetSymbolAddress((void**)&hB,  g_hbufB);
    cudaGetSymbolAddress((void**)&agg, g_agg);
    cudaGetSymbolAddress((void**)&z1,  g_z1);
    cudaGetSymbolAddress((void**)&z2,  g_z2);
    cudaGetSymbolAddress((void**)&Ahi, g_Ahi);
    cudaGetSymbolAddress((void**)&Alo, g_Alo);
    cudaGetSymbolAddress((void**)&Bhi, g_Bhi);
    cudaGetSymbolAddress((void**)&Blo, g_Blo);

    const int SMEM_BYTES = 3 * 32768;   // 96 KB -> 2 CTAs/SM
    cudaFuncSetAttribute(gemm_lean, cudaFuncAttributeMaxDynamicSharedMemorySize, SMEM_BYTES);

    const int elems = Nn * EMB;
    const int mtiles = (Nn + 127) / 128;
    const float* hin = x;

    agg_init<<<(elems + 255) / 256, 256>>>(x, eps, 0);

    for (int l = 0; l < LAYERS; l++) {
        float* hout = (l == LAYERS - 1) ? out : ((l & 1) ? hB : hA);

        prep1<<<NPAD1 + 10, 320>>>(W1 + (size_t)l * EMB2 * EMB, Wb + (size_t)l * EMB * 9);

        edge_msg<<<(Ee + EDGES_PER_BLOCK - 1) / EDGES_PER_BLOCK, 256>>>(hin, ei, ea);

        // split agg -> Ahi/Alo (KP1)
        split_A<0, EMB, KP1><<<(Nn * (KP1 / 4) + 255) / 256, 256>>>(agg);

        // GEMM1: z1 = agg @ W1^T  (stats fused)
        gemm_lean<<<dim3(NPAD1 / 128, mtiles), 256, SMEM_BYTES>>>(
            Ahi, Alo, Bhi, Blo, z1, Nn, EMB2, KP1, NCH1);

        // prep2: W2 split + BN1 finalize + (ordered) zero stats300
        prep2<<<NPAD2 + 1, 320>>>(W2 + (size_t)l * EMB * EMB2,
                                  bn1g + (size_t)l * EMB2, bn1b + (size_t)l * EMB2);

        // split relu(BN1(z1)) -> Ahi/Alo (KP2)
        split_A<1, EMB2, KP2><<<(Nn * (KP2 / 4) + 255) / 256, 256>>>(z1);

        // GEMM2: z2 = relu(BN1(z1)) @ W2^T  (stats fused)
        gemm_lean<<<dim3(NPAD2 / 128, mtiles), 256, SMEM_BYTES>>>(
            Ahi, Alo, Bhi, Blo, z2, Nn, EMB, KP2, NCH2);

        bn_finalize2<<<1, 320>>>(bng + (size_t)l * EMB, bnb + (size_t)l * EMB);

        bn_apply_agg<<<(elems + 255) / 256, 256>>>(z2, hout, eps,
                                                   (l < LAYERS - 1) ? l + 1 : 0,
                                                   (l < LAYERS - 1) ? 1 : 0,
                                                   (l < LAYERS - 1) ? 1 : 0);
        hin = hout;
    }
}

// round 11
// speedup vs baseline: 1.3165x; 1.3165x over previous
#include <cuda_runtime.h>
#include <cuda_bf16.h>
#include <cstdint>
#include <cstddef>

#define Nn   100000
#define Ee   256000
#define EMB  300
#define EMB2 600
#define LAYERS 5

#define KP1 320
#define KP2 640
#define NCHA 10     // KP1/32
#define NCHB 20     // KP2/32
#define NPAD1 640   // 5 n-tiles of 128
#define NPAD2 384   // 3 n-tiles of 128

// ---------------- device scratch ----------------
__device__ __align__(128) float  g_hbufA[(size_t)Nn * EMB];
__device__ __align__(128) float  g_hbufB[(size_t)Nn * EMB];
__device__ __align__(128) float  g_agg  [(size_t)Nn * EMB];
__device__ __align__(128) float  g_z1   [(size_t)Nn * EMB2];
__device__ __align__(128) float  g_z2   [(size_t)Nn * EMB];
__device__ __align__(128) __nv_bfloat16 g_Ahi[(size_t)Nn * KP2];
__device__ __align__(128) __nv_bfloat16 g_Alo[(size_t)Nn * KP2];
__device__ __align__(128) __nv_bfloat16 g_Bhi[262144];
__device__ __align__(128) __nv_bfloat16 g_Blo[262144];
__device__ __align__(16) float g_etab [9 * EMB];
__device__ double g_sum  [EMB2];
__device__ double g_sq   [EMB2];
__device__ float  g_sc1  [EMB2];
__device__ float  g_sh1  [EMB2];
__device__ float  g_sc2  [EMB];
__device__ float  g_sh2  [EMB];

// ---------------- PTX helpers ----------------
__device__ __forceinline__ uint32_t smem_u32(const void* p) {
    uint32_t a;
    asm("{ .reg .u64 t; cvta.to.shared.u64 t, %1; cvt.u32.u64 %0, t; }" : "=r"(a) : "l"(p));
    return a;
}
__device__ __forceinline__ void cp_async16(uint32_t dst, const void* src) {
    asm volatile("cp.async.cg.shared.global [%0], [%1], 16;" :: "r"(dst), "l"(src));
}
__device__ __forceinline__ void cp_async16p(uint32_t dst, const void* src, bool valid) {
    int sz = valid ? 16 : 0;
    asm volatile("cp.async.cg.shared.global [%0], [%1], 16, %2;" :: "r"(dst), "l"(src), "r"(sz));
}
__device__ __forceinline__ void cp_commit() { asm volatile("cp.async.commit_group;"); }
__device__ __forceinline__ uint32_t swz64(uint32_t b) { return b ^ ((b >> 3) & 0x30); }

__device__ __forceinline__ void ldsm_x4(uint32_t (&r)[4], uint32_t addr) {
    asm volatile("ldmatrix.sync.aligned.m8n8.x4.shared.b16 {%0,%1,%2,%3}, [%4];"
        : "=r"(r[0]), "=r"(r[1]), "=r"(r[2]), "=r"(r[3]) : "r"(addr));
}
__device__ __forceinline__ void mma16816(float (&d)[4], const uint32_t (&a)[4],
                                         uint32_t b0, uint32_t b1) {
    asm volatile("mma.sync.aligned.m16n8k16.row.col.f32.bf16.bf16.f32 "
        "{%0,%1,%2,%3}, {%4,%5,%6,%7}, {%8,%9}, {%0,%1,%2,%3};"
        : "+f"(d[0]), "+f"(d[1]), "+f"(d[2]), "+f"(d[3])
        : "r"(a[0]), "r"(a[1]), "r"(a[2]), "r"(a[3]), "r"(b0), "r"(b1));
}
__device__ __forceinline__ void red_add_v4(float* addr, float a, float b, float c, float d) {
    asm volatile("red.global.add.v4.f32 [%0], {%1,%2,%3,%4};"
        :: "l"(addr), "f"(a), "f"(b), "f"(c), "f"(d) : "memory");
}

// ---------------- elementwise / prep kernels ----------------
__global__ void agg_init(const float* __restrict__ h, const float* __restrict__ eps, int l) {
    int i = blockIdx.x * blockDim.x + threadIdx.x;
    if (i < Nn * EMB) g_agg[i] = (1.0f + __ldg(eps + l)) * h[i];
}

__global__ void prep1(const float* __restrict__ W1, const float* __restrict__ Wb) {
    int b = blockIdx.x, t = threadIdx.x;
    if (b < NPAD1) {
        float v = (b < EMB2 && t < EMB) ? W1[(size_t)b * EMB + t] : 0.0f;
        __nv_bfloat16 h = __float2bfloat16_rn(v);
        g_Bhi[(size_t)b * KP1 + t] = h;
        g_Blo[(size_t)b * KP1 + t] = __float2bfloat16_rn(v - __bfloat162float(h));
    } else if (b < NPAD1 + 9) {
        int c = b - NPAD1;
        if (t < EMB) g_etab[c * EMB + t] = Wb[t * 9 + c / 3] + Wb[t * 9 + 6 + (c % 3)];
    } else {
        for (int i = t; i < EMB2; i += blockDim.x) { g_sum[i] = 0.0; g_sq[i] = 0.0; }
    }
}

__global__ void prep2(const float* __restrict__ W2,
                      const float* __restrict__ gamma, const float* __restrict__ beta) {
    int b = blockIdx.x, t = threadIdx.x;
    if (b < NPAD2) {
        for (int c = t; c < KP2; c += blockDim.x) {
            float v = (b < EMB && c < EMB2) ? W2[(size_t)b * EMB2 + c] : 0.0f;
            __nv_bfloat16 h = __float2bfloat16_rn(v);
            g_Bhi[(size_t)b * KP2 + c] = h;
            g_Blo[(size_t)b * KP2 + c] = __float2bfloat16_rn(v - __bfloat162float(h));
        }
    } else {
        for (int i = t; i < EMB2; i += blockDim.x) {
            double m = g_sum[i] / (double)Nn;
            double v = g_sq[i] / (double)Nn - m * m;
            float rs = rsqrtf((float)v + 1e-5f);
            float a = gamma[i] * rs;
            g_sc1[i] = a;
            g_sh1[i] = beta[i] - a * (float)m;
        }
        __syncthreads();
        for (int i = t; i < EMB; i += blockDim.x) { g_sum[i] = 0.0; g_sq[i] = 0.0; }
    }
}

__global__ void bn_finalize2(const float* __restrict__ gamma, const float* __restrict__ beta) {
    int i = blockIdx.x * blockDim.x + threadIdx.x;
    if (i >= EMB) return;
    double m = g_sum[i] / (double)Nn;
    double v = g_sq[i] / (double)Nn - m * m;
    float rs = rsqrtf((float)v + 1e-5f);
    float a = gamma[i] * rs;
    g_sc2[i] = a;
    g_sh2[i] = beta[i] - a * (float)m;
}

__global__ void bn_apply_agg(const float* __restrict__ Z, float* __restrict__ outh,
                             const float* __restrict__ eps, int lnext, int relu, int wagg) {
    int i = blockIdx.x * blockDim.x + threadIdx.x;
    if (i >= Nn * EMB) return;
    int col = i % EMB;
    float v = fmaf(g_sc2[col], Z[i], g_sh2[col]);
    if (relu) v = fmaxf(v, 0.0f);
    outh[i] = v;
    if (wagg) g_agg[i] = (1.0f + __ldg(eps + lnext)) * v;
}

// ---------------- standalone A split: fp32 -> bf16 hi/lo, float4 vectorized ----------
template <int TRANSFORM, int K, int KP>
__global__ void __launch_bounds__(256)
split_A(const float* __restrict__ src) {
    const int qpr = KP / 4;
    int i = blockIdx.x * blockDim.x + threadIdx.x;
    if (i >= Nn * qpr) return;
    int row = i / qpr;
    int col = (i - row * qpr) * 4;
    float4 v = make_float4(0.f, 0.f, 0.f, 0.f);
    if (col < K) {
        v = *reinterpret_cast<const float4*>(src + (size_t)row * K + col);
        if (TRANSFORM) {
            float4 cs = *reinterpret_cast<const float4*>(g_sc1 + col);
            float4 ds = *reinterpret_cast<const float4*>(g_sh1 + col);
            v.x = fmaxf(fmaf(cs.x, v.x, ds.x), 0.f);
            v.y = fmaxf(fmaf(cs.y, v.y, ds.y), 0.f);
            v.z = fmaxf(fmaf(cs.z, v.z, ds.z), 0.f);
            v.w = fmaxf(fmaf(cs.w, v.w, ds.w), 0.f);
        }
    }
    __nv_bfloat162 H0 = __floats2bfloat162_rn(v.x, v.y);
    __nv_bfloat162 H1 = __floats2bfloat162_rn(v.z, v.w);
    __nv_bfloat162 L0 = __floats2bfloat162_rn(v.x - __low2float(H0), v.y - __high2float(H0));
    __nv_bfloat162 L1 = __floats2bfloat162_rn(v.z - __low2float(H1), v.w - __high2float(H1));
    uint2 hv = make_uint2(*reinterpret_cast<uint32_t*>(&H0), *reinterpret_cast<uint32_t*>(&H1));
    uint2 lv = make_uint2(*reinterpret_cast<uint32_t*>(&L0), *reinterpret_cast<uint32_t*>(&L1));
    *reinterpret_cast<uint2*>(g_Ahi + (size_t)row * KP + col) = hv;
    *reinterpret_cast<uint2*>(g_Alo + (size_t)row * KP + col) = lv;
}

// ---------------- edge scatter (unchanged) ----------------
#define EDGES_PER_BLOCK 64
__global__ void __launch_bounds__(256)
edge_msg(const float* __restrict__ h, const int* __restrict__ ei,
         const int* __restrict__ ea) {
    __shared__ __align__(16) float s_et[9 * EMB];
    for (int i = threadIdx.x; i < 9 * EMB; i += blockDim.x) s_et[i] = g_etab[i];
    __syncthreads();

    int warp = threadIdx.x >> 5, lane = threadIdx.x & 31;
    int ebase = blockIdx.x * EDGES_PER_BLOCK + warp * (EDGES_PER_BLOCK / 8);

#pragma unroll
    for (int u = 0; u < EDGES_PER_BLOCK / 8; u++) {
        int e = ebase + u;
        if (e >= Ee) return;
        int src = __ldg(ei + e);
        int dst = __ldg(ei + Ee + e);
        int c   = __ldg(ea + 2 * e) * 3 + __ldg(ea + 2 * e + 1);

        const float4* hr = reinterpret_cast<const float4*>(h + (size_t)src * EMB);
        float*        ar = g_agg + (size_t)dst * EMB;
        const float4* er = reinterpret_cast<const float4*>(s_et + c * EMB);

#pragma unroll
        for (int it = 0; it < 3; it++) {
            int k = lane + it * 32;
            if (k < 75) {
                float4 hv = __ldg(hr + k);
                float4 ev = er[k];
                float a = fmaxf(hv.x + ev.x, 0.0f);
                float b = fmaxf(hv.y + ev.y, 0.0f);
                float cc = fmaxf(hv.z + ev.z, 0.0f);
                float d = fmaxf(hv.w + ev.w, 0.0f);
                if (a + b + cc + d > 0.0f)
                    red_add_v4(ar + k * 4, a, b, cc, d);
            }
        }
    }
}

// ---------------- split-bf16 GEMM, K-chunk 32, 3-stage, 2 CTAs/SM ----------------
// Per chunk: one barrier, 3 MMA phases (hh, lh, hl) = 96 MMA/warp.
// Stage layout (32KB): Ah@0(8K) Al@8K Bh@16K Bl@24K. SW64 swizzle (64B rows).
__global__ void __launch_bounds__(256, 2)
gemm_s32(const __nv_bfloat16* __restrict__ Ahi, const __nv_bfloat16* __restrict__ Alo,
         const __nv_bfloat16* __restrict__ Bhi, const __nv_bfloat16* __restrict__ Blo,
         float* __restrict__ C, int M, int NC, int KP, int nch) {
    extern __shared__ __align__(1024) char smem[];
    uint32_t sb = smem_u32(smem);

    int tid = threadIdx.x;
    int wid = tid >> 5, lane = tid & 31;
    int wm = wid >> 2, wn = wid & 3;        // 2(M) x 4(N)
    int n0 = blockIdx.x * 128;              // n fastest -> A L2 reuse
    int m0 = blockIdx.y * 128;

    int quad = lane >> 3, r = lane & 7;
    int arow_base = wm * 64 + (quad & 1) * 8 + r;
    int brow_base = wn * 32 + (quad & 1) * 8 + r;
    int khalf = quad >> 1;                  // 16B half within a k16 block

    float acc[4][4][4];
#pragma unroll
    for (int mi = 0; mi < 4; mi++)
#pragma unroll
        for (int nt = 0; nt < 4; nt++)
#pragma unroll
            for (int q = 0; q < 4; q++) acc[mi][nt][q] = 0.0f;

    auto load_chunk = [&](int kc, int buf) {
        uint32_t s0 = sb + buf * 32768;
        size_t aoff = (size_t)m0 * KP + (size_t)kc * 32;
        size_t boff = (size_t)n0 * KP + (size_t)kc * 32;
#pragma unroll
        for (int i = 0; i < 2; i++) {
            int seg = tid + i * 256;        // 0..511
            int row = seg >> 2, s = seg & 3;
            uint32_t so = swz64(row * 64 + s * 16);
            size_t ra = aoff + (size_t)row * KP + s * 8;
            size_t rb = boff + (size_t)row * KP + s * 8;
            bool va = (m0 + row) < M;
            cp_async16p(s0 + so,          Ahi + ra, va);
            cp_async16p(s0 + 8192 + so,   Alo + ra, va);
            cp_async16(s0 + 16384 + so,   Bhi + rb);
            cp_async16(s0 + 24576 + so,   Blo + rb);
        }
        cp_commit();
    };

    load_chunk(0, 0);
    load_chunk(1, 1);

    for (int j = 0; j < nch; j++) {
        if (j + 2 < nch) asm volatile("cp.async.wait_group 1;" ::: "memory");
        else             asm volatile("cp.async.wait_group 0;" ::: "memory");
        __syncthreads();

        if (j + 2 < nch) load_chunk(j + 2, (j + 2) % 3);

        uint32_t s0 = sb + (j % 3) * 32768;
#pragma unroll
        for (int p = 0; p < 3; p++) {
            uint32_t sA = s0 + ((p == 1) ? 8192 : 0);
            uint32_t sB = s0 + 16384 + ((p == 2) ? 8192 : 0);
#pragma unroll
            for (int ks = 0; ks < 2; ks++) {
                int seg = ks * 2 + khalf;
                uint32_t a[4][4];
#pragma unroll
                for (int mi = 0; mi < 4; mi++)
                    ldsm_x4(a[mi], sA + swz64((arow_base + mi * 16) * 64 + seg * 16));
                uint32_t b[2][4];
#pragma unroll
                for (int nj = 0; nj < 2; nj++)
                    ldsm_x4(b[nj], sB + swz64((brow_base + nj * 16) * 64 + seg * 16));
#pragma unroll
                for (int mi = 0; mi < 4; mi++)
#pragma unroll
                    for (int nt = 0; nt < 4; nt++)
                        mma16816(acc[mi][nt], a[mi], b[nt >> 1][nt & 1], b[nt >> 1][(nt & 1) + 2]);
            }
        }
    }

    // ---- epilogue: C stores ----
    int rg = lane >> 2, cg = (lane & 3) * 2;
#pragma unroll
    for (int mi = 0; mi < 4; mi++) {
        int r0 = m0 + wm * 64 + mi * 16 + rg;
#pragma unroll
        for (int nt = 0; nt < 4; nt++) {
            int c0 = n0 + wn * 32 + nt * 8 + cg;
            if (c0 < NC) {
                if (r0 < M)
                    *reinterpret_cast<float2*>(C + (size_t)r0 * NC + c0) =
                        make_float2(acc[mi][nt][0], acc[mi][nt][1]);
                if (r0 + 8 < M)
                    *reinterpret_cast<float2*>(C + (size_t)(r0 + 8) * NC + c0) =
                        make_float2(acc[mi][nt][2], acc[mi][nt][3]);
            }
        }
    }

    // ---- epilogue: fused BN stats (padded rows zero-filled => contribute 0) ----
#pragma unroll
    for (int nt = 0; nt < 4; nt++) {
#pragma unroll
        for (int cp = 0; cp < 2; cp++) {
            float s = 0.f, q = 0.f;
#pragma unroll
            for (int mi = 0; mi < 4; mi++) {
                float v0 = acc[mi][nt][cp];
                float v1 = acc[mi][nt][cp + 2];
                s += v0 + v1;
                q += v0 * v0 + v1 * v1;
            }
#pragma unroll
            for (int off = 4; off <= 16; off <<= 1) {
                s += __shfl_xor_sync(0xFFFFFFFF, s, off);
                q += __shfl_xor_sync(0xFFFFFFFF, q, off);
            }
            if ((lane >> 2) == 0) {
                int c0 = n0 + wn * 32 + nt * 8 + (lane & 3) * 2 + cp;
                if (c0 < NC) {
                    atomicAdd(&g_sum[c0], (double)s);
                    atomicAdd(&g_sq[c0], (double)q);
                }
            }
        }
    }
}

// ---------------- launcher ----------------
extern "C" void kernel_launch(void* const* d_in, const int* in_sizes, int n_in,
                              void* d_out, int out_size) {
    const float* x    = (const float*)d_in[0];
    const float* Wb   = (const float*)d_in[1];
    const float* eps  = (const float*)d_in[2];
    const float* W1   = (const float*)d_in[3];
    const float* bn1g = (const float*)d_in[5];
    const float* bn1b = (const float*)d_in[6];
    const float* W2   = (const float*)d_in[7];
    const float* bng  = (const float*)d_in[9];
    const float* bnb  = (const float*)d_in[10];
    const int*   ei   = (const int*)d_in[11];
    const int*   ea   = (const int*)d_in[12];
    float* out = (float*)d_out;

    float *hA, *hB, *agg, *z1, *z2;
    __nv_bfloat16 *Ahi, *Alo, *Bhi, *Blo;
    cudaGetSymbolAddress((void**)&hA,  g_hbufA);
    cudaGetSymbolAddress((void**)&hB,  g_hbufB);
    cudaGetSymbolAddress((void**)&agg, g_agg);
    cudaGetSymbolAddress((void**)&z1,  g_z1);
    cudaGetSymbolAddress((void**)&z2,  g_z2);
    cudaGetSymbolAddress((void**)&Ahi, g_Ahi);
    cudaGetSymbolAddress((void**)&Alo, g_Alo);
    cudaGetSymbolAddress((void**)&Bhi, g_Bhi);
    cudaGetSymbolAddress((void**)&Blo, g_Blo);

    const int SMEM_BYTES = 3 * 32768;   // 96 KB -> 2 CTAs/SM
    cudaFuncSetAttribute(gemm_s32, cudaFuncAttributeMaxDynamicSharedMemorySize, SMEM_BYTES);

    const int elems = Nn * EMB;
    const int mtiles = (Nn + 127) / 128;
    const float* hin = x;

    agg_init<<<(elems + 255) / 256, 256>>>(x, eps, 0);

    for (int l = 0; l < LAYERS; l++) {
        float* hout = (l == LAYERS - 1) ? out : ((l & 1) ? hB : hA);

        prep1<<<NPAD1 + 10, 320>>>(W1 + (size_t)l * EMB2 * EMB, Wb + (size_t)l * EMB * 9);

        edge_msg<<<(Ee + EDGES_PER_BLOCK - 1) / EDGES_PER_BLOCK, 256>>>(hin, ei, ea);

        split_A<0, EMB, KP1><<<(Nn * (KP1 / 4) + 255) / 256, 256>>>(agg);

        // GEMM1: z1 = agg @ W1^T  (stats fused)
        gemm_s32<<<dim3(NPAD1 / 128, mtiles), 256, SMEM_BYTES>>>(
            Ahi, Alo, Bhi, Blo, z1, Nn, EMB2, KP1, NCHA);

        prep2<<<NPAD2 + 1, 320>>>(W2 + (size_t)l * EMB * EMB2,
                                  bn1g + (size_t)l * EMB2, bn1b + (size_t)l * EMB2);

        split_A<1, EMB2, KP2><<<(Nn * (KP2 / 4) + 255) / 256, 256>>>(z1);

        // GEMM2: z2 = relu(BN1(z1)) @ W2^T  (stats fused)
        gemm_s32<<<dim3(NPAD2 / 128, mtiles), 256, SMEM_BYTES>>>(
            Ahi, Alo, Bhi, Blo, z2, Nn, EMB, KP2, NCHB);

        bn_finalize2<<<1, 320>>>(bng + (size_t)l * EMB, bnb + (size_t)l * EMB);

        bn_apply_agg<<<(elems + 255) / 256, 256>>>(z2, hout, eps,
                                                   (l < LAYERS - 1) ? l + 1 : 0,
                                                   (l < LAYERS - 1) ? 1 : 0,
                                                   (l < LAYERS - 1) ? 1 : 0);
        hin = hout;
    }
}

// round 12
// speedup vs baseline: 1.4345x; 1.0896x over previous
#include <cuda_runtime.h>
#include <cuda_bf16.h>
#include <cstdint>
#include <cstddef>

#define Nn   100000
#define Ee   256000
#define EMB  300
#define EMB2 600
#define LAYERS 5

#define KP1 320
#define KP2 640
#define NCHA 10     // KP1/32
#define NCHB 20     // KP2/32
#define NPAD1 640   // 5 n-tiles of 128
#define NPAD2 384   // 3 n-tiles of 128

// ---------------- device scratch ----------------
__device__ __align__(128) float  g_hbufA[(size_t)Nn * EMB];
__device__ __align__(128) float  g_hbufB[(size_t)Nn * EMB];
__device__ __align__(128) float  g_agg  [(size_t)Nn * EMB];
__device__ __align__(128) float  g_z1   [(size_t)Nn * EMB2];
__device__ __align__(128) float  g_z2   [(size_t)Nn * EMB];
__device__ __align__(128) __nv_bfloat16 g_Ahi[(size_t)Nn * KP2];
__device__ __align__(128) __nv_bfloat16 g_Alo[(size_t)Nn * KP2];
__device__ __align__(128) __nv_bfloat16 g_Bhi[262144];
__device__ __align__(128) __nv_bfloat16 g_Blo[262144];
__device__ __align__(16) float g_etab [9 * EMB];
__device__ double g_sum  [EMB2];
__device__ double g_sq   [EMB2];
__device__ float  g_sc1  [EMB2];
__device__ float  g_sh1  [EMB2];
__device__ float  g_sc2  [EMB];
__device__ float  g_sh2  [EMB];

// ---------------- PTX helpers ----------------
__device__ __forceinline__ uint32_t smem_u32(const void* p) {
    uint32_t a;
    asm("{ .reg .u64 t; cvta.to.shared.u64 t, %1; cvt.u32.u64 %0, t; }" : "=r"(a) : "l"(p));
    return a;
}
__device__ __forceinline__ void cp_async16(uint32_t dst, const void* src) {
    asm volatile("cp.async.cg.shared.global [%0], [%1], 16;" :: "r"(dst), "l"(src));
}
__device__ __forceinline__ void cp_async16p(uint32_t dst, const void* src, bool valid) {
    int sz = valid ? 16 : 0;
    asm volatile("cp.async.cg.shared.global [%0], [%1], 16, %2;" :: "r"(dst), "l"(src), "r"(sz));
}
__device__ __forceinline__ void cp_commit() { asm volatile("cp.async.commit_group;"); }
__device__ __forceinline__ uint32_t swz64(uint32_t b) { return b ^ ((b >> 3) & 0x30); }

__device__ __forceinline__ void ldsm_x4(uint32_t (&r)[4], uint32_t addr) {
    asm volatile("ldmatrix.sync.aligned.m8n8.x4.shared.b16 {%0,%1,%2,%3}, [%4];"
        : "=r"(r[0]), "=r"(r[1]), "=r"(r[2]), "=r"(r[3]) : "r"(addr));
}
__device__ __forceinline__ void mma16816(float (&d)[4], const uint32_t (&a)[4],
                                         uint32_t b0, uint32_t b1) {
    asm volatile("mma.sync.aligned.m16n8k16.row.col.f32.bf16.bf16.f32 "
        "{%0,%1,%2,%3}, {%4,%5,%6,%7}, {%8,%9}, {%0,%1,%2,%3};"
        : "+f"(d[0]), "+f"(d[1]), "+f"(d[2]), "+f"(d[3])
        : "r"(a[0]), "r"(a[1]), "r"(a[2]), "r"(a[3]), "r"(b0), "r"(b1));
}
__device__ __forceinline__ void red_add_v4(float* addr, float a, float b, float c, float d) {
    asm volatile("red.global.add.v4.f32 [%0], {%1,%2,%3,%4};"
        :: "l"(addr), "f"(a), "f"(b), "f"(c), "f"(d) : "memory");
}

// ---------------- elementwise / prep kernels ----------------
__global__ void agg_init(const float* __restrict__ h, const float* __restrict__ eps, int l) {
    int i = blockIdx.x * blockDim.x + threadIdx.x;
    if (i < Nn * EMB) g_agg[i] = (1.0f + __ldg(eps + l)) * h[i];
}

__global__ void prep1(const float* __restrict__ W1, const float* __restrict__ Wb) {
    int b = blockIdx.x, t = threadIdx.x;
    if (b < NPAD1) {
        float v = (b < EMB2 && t < EMB) ? W1[(size_t)b * EMB + t] : 0.0f;
        __nv_bfloat16 h = __float2bfloat16_rn(v);
        g_Bhi[(size_t)b * KP1 + t] = h;
        g_Blo[(size_t)b * KP1 + t] = __float2bfloat16_rn(v - __bfloat162float(h));
    } else if (b < NPAD1 + 9) {
        int c = b - NPAD1;
        if (t < EMB) g_etab[c * EMB + t] = Wb[t * 9 + c / 3] + Wb[t * 9 + 6 + (c % 3)];
    } else {
        for (int i = t; i < EMB2; i += blockDim.x) { g_sum[i] = 0.0; g_sq[i] = 0.0; }
    }
}

__global__ void prep2(const float* __restrict__ W2,
                      const float* __restrict__ gamma, const float* __restrict__ beta) {
    int b = blockIdx.x, t = threadIdx.x;
    if (b < NPAD2) {
        for (int c = t; c < KP2; c += blockDim.x) {
            float v = (b < EMB && c < EMB2) ? W2[(size_t)b * EMB2 + c] : 0.0f;
            __nv_bfloat16 h = __float2bfloat16_rn(v);
            g_Bhi[(size_t)b * KP2 + c] = h;
            g_Blo[(size_t)b * KP2 + c] = __float2bfloat16_rn(v - __bfloat162float(h));
        }
    } else {
        for (int i = t; i < EMB2; i += blockDim.x) {
            double m = g_sum[i] / (double)Nn;
            double v = g_sq[i] / (double)Nn - m * m;
            float rs = rsqrtf((float)v + 1e-5f);
            float a = gamma[i] * rs;
            g_sc1[i] = a;
            g_sh1[i] = beta[i] - a * (float)m;
        }
        __syncthreads();
        for (int i = t; i < EMB; i += blockDim.x) { g_sum[i] = 0.0; g_sq[i] = 0.0; }
    }
}

__global__ void bn_finalize2(const float* __restrict__ gamma, const float* __restrict__ beta) {
    int i = blockIdx.x * blockDim.x + threadIdx.x;
    if (i >= EMB) return;
    double m = g_sum[i] / (double)Nn;
    double v = g_sq[i] / (double)Nn - m * m;
    float rs = rsqrtf((float)v + 1e-5f);
    float a = gamma[i] * rs;
    g_sc2[i] = a;
    g_sh2[i] = beta[i] - a * (float)m;
}

__global__ void bn_apply_agg(const float* __restrict__ Z, float* __restrict__ outh,
                             const float* __restrict__ eps, int lnext, int relu, int wagg) {
    int i = blockIdx.x * blockDim.x + threadIdx.x;
    if (i >= Nn * EMB) return;
    int col = i % EMB;
    float v = fmaf(g_sc2[col], Z[i], g_sh2[col]);
    if (relu) v = fmaxf(v, 0.0f);
    outh[i] = v;
    if (wagg) g_agg[i] = (1.0f + __ldg(eps + lnext)) * v;
}

// ---------------- standalone A split ----------------
template <int TRANSFORM, int K, int KP>
__global__ void __launch_bounds__(256)
split_A(const float* __restrict__ src) {
    const int qpr = KP / 4;
    int i = blockIdx.x * blockDim.x + threadIdx.x;
    if (i >= Nn * qpr) return;
    int row = i / qpr;
    int col = (i - row * qpr) * 4;
    float4 v = make_float4(0.f, 0.f, 0.f, 0.f);
    if (col < K) {
        v = *reinterpret_cast<const float4*>(src + (size_t)row * K + col);
        if (TRANSFORM) {
            float4 cs = *reinterpret_cast<const float4*>(g_sc1 + col);
            float4 ds = *reinterpret_cast<const float4*>(g_sh1 + col);
            v.x = fmaxf(fmaf(cs.x, v.x, ds.x), 0.f);
            v.y = fmaxf(fmaf(cs.y, v.y, ds.y), 0.f);
            v.z = fmaxf(fmaf(cs.z, v.z, ds.z), 0.f);
            v.w = fmaxf(fmaf(cs.w, v.w, ds.w), 0.f);
        }
    }
    __nv_bfloat162 H0 = __floats2bfloat162_rn(v.x, v.y);
    __nv_bfloat162 H1 = __floats2bfloat162_rn(v.z, v.w);
    __nv_bfloat162 L0 = __floats2bfloat162_rn(v.x - __low2float(H0), v.y - __high2float(H0));
    __nv_bfloat162 L1 = __floats2bfloat162_rn(v.z - __low2float(H1), v.w - __high2float(H1));
    uint2 hv = make_uint2(*reinterpret_cast<uint32_t*>(&H0), *reinterpret_cast<uint32_t*>(&H1));
    uint2 lv = make_uint2(*reinterpret_cast<uint32_t*>(&L0), *reinterpret_cast<uint32_t*>(&L1));
    *reinterpret_cast<uint2*>(g_Ahi + (size_t)row * KP + col) = hv;
    *reinterpret_cast<uint2*>(g_Alo + (size_t)row * KP + col) = lv;
}

// ---------------- edge scatter (unchanged) ----------------
#define EDGES_PER_BLOCK 64
__global__ void __launch_bounds__(256)
edge_msg(const float* __restrict__ h, const int* __restrict__ ei,
         const int* __restrict__ ea) {
    __shared__ __align__(16) float s_et[9 * EMB];
    for (int i = threadIdx.x; i < 9 * EMB; i += blockDim.x) s_et[i] = g_etab[i];
    __syncthreads();

    int warp = threadIdx.x >> 5, lane = threadIdx.x & 31;
    int ebase = blockIdx.x * EDGES_PER_BLOCK + warp * (EDGES_PER_BLOCK / 8);

#pragma unroll
    for (int u = 0; u < EDGES_PER_BLOCK / 8; u++) {
        int e = ebase + u;
        if (e >= Ee) return;
        int src = __ldg(ei + e);
        int dst = __ldg(ei + Ee + e);
        int c   = __ldg(ea + 2 * e) * 3 + __ldg(ea + 2 * e + 1);

        const float4* hr = reinterpret_cast<const float4*>(h + (size_t)src * EMB);
        float*        ar = g_agg + (size_t)dst * EMB;
        const float4* er = reinterpret_cast<const float4*>(s_et + c * EMB);

#pragma unroll
        for (int it = 0; it < 3; it++) {
            int k = lane + it * 32;
            if (k < 75) {
                float4 hv = __ldg(hr + k);
                float4 ev = er[k];
                float a = fmaxf(hv.x + ev.x, 0.0f);
                float b = fmaxf(hv.y + ev.y, 0.0f);
                float cc = fmaxf(hv.z + ev.z, 0.0f);
                float d = fmaxf(hv.w + ev.w, 0.0f);
                if (a + b + cc + d > 0.0f)
                    red_add_v4(ar + k * 4, a, b, cc, d);
            }
        }
    }
}

// ---------------- split-bf16 GEMM, K-chunk 32, frag-reuse phase order ----------------
// Per k16 segment: hh (Ah,Bh) -> hl (Ah,Bl) -> lh (Al,Bh). Ah/Bh loaded once.
// LDSM per chunk/warp: 12 ops (was 18). Stage 32KB: Ah@0 Al@8K Bh@16K Bl@24K, SW64.
__global__ void __launch_bounds__(256, 2)
gemm_s32(const __nv_bfloat16* __restrict__ Ahi, const __nv_bfloat16* __restrict__ Alo,
         const __nv_bfloat16* __restrict__ Bhi, const __nv_bfloat16* __restrict__ Blo,
         float* __restrict__ C, int M, int NC, int KP, int nch) {
    extern __shared__ __align__(1024) char smem[];
    uint32_t sb = smem_u32(smem);

    int tid = threadIdx.x;
    int wid = tid >> 5, lane = tid & 31;
    int wm = wid >> 2, wn = wid & 3;        // 2(M) x 4(N)
    int n0 = blockIdx.x * 128;
    int m0 = blockIdx.y * 128;

    int quad = lane >> 3, r = lane & 7;
    int arow_base = wm * 64 + (quad & 1) * 8 + r;
    int brow_base = wn * 32 + (quad & 1) * 8 + r;
    int khalf = quad >> 1;

    float acc[4][4][4];
#pragma unroll
    for (int mi = 0; mi < 4; mi++)
#pragma unroll
        for (int nt = 0; nt < 4; nt++)
#pragma unroll
            for (int q = 0; q < 4; q++) acc[mi][nt][q] = 0.0f;

    auto load_chunk = [&](int kc, int buf) {
        uint32_t s0 = sb + buf * 32768;
        size_t aoff = (size_t)m0 * KP + (size_t)kc * 32;
        size_t boff = (size_t)n0 * KP + (size_t)kc * 32;
#pragma unroll
        for (int i = 0; i < 2; i++) {
            int seg = tid + i * 256;
            int row = seg >> 2, s = seg & 3;
            uint32_t so = swz64(row * 64 + s * 16);
            size_t ra = aoff + (size_t)row * KP + s * 8;
            size_t rb = boff + (size_t)row * KP + s * 8;
            bool va = (m0 + row) < M;
            cp_async16p(s0 + so,          Ahi + ra, va);
            cp_async16p(s0 + 8192 + so,   Alo + ra, va);
            cp_async16(s0 + 16384 + so,   Bhi + rb);
            cp_async16(s0 + 24576 + so,   Blo + rb);
        }
        cp_commit();
    };

    load_chunk(0, 0);
    load_chunk(1, 1);

    for (int j = 0; j < nch; j++) {
        if (j + 2 < nch) asm volatile("cp.async.wait_group 1;" ::: "memory");
        else             asm volatile("cp.async.wait_group 0;" ::: "memory");
        __syncthreads();

        if (j + 2 < nch) load_chunk(j + 2, (j + 2) % 3);

        uint32_t s0 = sb + (j % 3) * 32768;
#pragma unroll
        for (int ks = 0; ks < 2; ks++) {
            int seg = ks * 2 + khalf;
            uint32_t a[4][4], bh[2][4], bl[2][4];

            // --- load Ah + Bh fragments once ---
#pragma unroll
            for (int mi = 0; mi < 4; mi++)
                ldsm_x4(a[mi], s0 + swz64((arow_base + mi * 16) * 64 + seg * 16));
#pragma unroll
            for (int nj = 0; nj < 2; nj++)
                ldsm_x4(bh[nj], s0 + 16384 + swz64((brow_base + nj * 16) * 64 + seg * 16));

            // --- phase hh: Ah * Bh ---
#pragma unroll
            for (int mi = 0; mi < 4; mi++)
#pragma unroll
                for (int nt = 0; nt < 4; nt++)
                    mma16816(acc[mi][nt], a[mi], bh[nt >> 1][nt & 1], bh[nt >> 1][(nt & 1) + 2]);

            // --- load Bl; phase hl: Ah * Bl ---
#pragma unroll
            for (int nj = 0; nj < 2; nj++)
                ldsm_x4(bl[nj], s0 + 24576 + swz64((brow_base + nj * 16) * 64 + seg * 16));
#pragma unroll
            for (int mi = 0; mi < 4; mi++)
#pragma unroll
                for (int nt = 0; nt < 4; nt++)
                    mma16816(acc[mi][nt], a[mi], bl[nt >> 1][nt & 1], bl[nt >> 1][(nt & 1) + 2]);

            // --- load Al (reuse a[]); phase lh: Al * Bh ---
#pragma unroll
            for (int mi = 0; mi < 4; mi++)
                ldsm_x4(a[mi], s0 + 8192 + swz64((arow_base + mi * 16) * 64 + seg * 16));
#pragma unroll
            for (int mi = 0; mi < 4; mi++)
#pragma unroll
                for (int nt = 0; nt < 4; nt++)
                    mma16816(acc[mi][nt], a[mi], bh[nt >> 1][nt & 1], bh[nt >> 1][(nt & 1) + 2]);
        }
    }

    // ---- epilogue: C stores ----
    int rg = lane >> 2, cg = (lane & 3) * 2;
#pragma unroll
    for (int mi = 0; mi < 4; mi++) {
        int r0 = m0 + wm * 64 + mi * 16 + rg;
#pragma unroll
        for (int nt = 0; nt < 4; nt++) {
            int c0 = n0 + wn * 32 + nt * 8 + cg;
            if (c0 < NC) {
                if (r0 < M)
                    *reinterpret_cast<float2*>(C + (size_t)r0 * NC + c0) =
                        make_float2(acc[mi][nt][0], acc[mi][nt][1]);
                if (r0 + 8 < M)
                    *reinterpret_cast<float2*>(C + (size_t)(r0 + 8) * NC + c0) =
                        make_float2(acc[mi][nt][2], acc[mi][nt][3]);
            }
        }
    }

    // ---- epilogue: fused BN stats ----
#pragma unroll
    for (int nt = 0; nt < 4; nt++) {
#pragma unroll
        for (int cp = 0; cp < 2; cp++) {
            float s = 0.f, q = 0.f;
#pragma unroll
            for (int mi = 0; mi < 4; mi++) {
                float v0 = acc[mi][nt][cp];
                float v1 = acc[mi][nt][cp + 2];
                s += v0 + v1;
                q += v0 * v0 + v1 * v1;
            }
#pragma unroll
            for (int off = 4; off <= 16; off <<= 1) {
                s += __shfl_xor_sync(0xFFFFFFFF, s, off);
                q += __shfl_xor_sync(0xFFFFFFFF, q, off);
            }
            if ((lane >> 2) == 0) {
                int c0 = n0 + wn * 32 + nt * 8 + (lane & 3) * 2 + cp;
                if (c0 < NC) {
                    atomicAdd(&g_sum[c0], (double)s);
                    atomicAdd(&g_sq[c0], (double)q);
                }
            }
        }
    }
}

// ---------------- launcher ----------------
extern "C" void kernel_launch(void* const* d_in, const int* in_sizes, int n_in,
                              void* d_out, int out_size) {
    const float* x    = (const float*)d_in[0];
    const float* Wb   = (const float*)d_in[1];
    const float* eps  = (const float*)d_in[2];
    const float* W1   = (const float*)d_in[3];
    const float* bn1g = (const float*)d_in[5];
    const float* bn1b = (const float*)d_in[6];
    const float* W2   = (const float*)d_in[7];
    const float* bng  = (const float*)d_in[9];
    const float* bnb  = (const float*)d_in[10];
    const int*   ei   = (const int*)d_in[11];
    const int*   ea   = (const int*)d_in[12];
    float* out = (float*)d_out;

    float *hA, *hB, *agg, *z1, *z2;
    __nv_bfloat16 *Ahi, *Alo, *Bhi, *Blo;
    cudaGetSymbolAddress((void**)&hA,  g_hbufA);
    cudaGetSymbolAddress((void**)&hB,  g_hbufB);
    cudaGetSymbolAddress((void**)&agg, g_agg);
    cudaGetSymbolAddress((void**)&z1,  g_z1);
    cudaGetSymbolAddress((void**)&z2,  g_z2);
    cudaGetSymbolAddress((void**)&Ahi, g_Ahi);
    cudaGetSymbolAddress((void**)&Alo, g_Alo);
    cudaGetSymbolAddress((void**)&Bhi, g_Bhi);
    cudaGetSymbolAddress((void**)&Blo, g_Blo);

    const int SMEM_BYTES = 3 * 32768;   // 96 KB -> 2 CTAs/SM
    cudaFuncSetAttribute(gemm_s32, cudaFuncAttributeMaxDynamicSharedMemorySize, SMEM_BYTES);

    const int elems = Nn * EMB;
    const int mtiles = (Nn + 127) / 128;
    const float* hin = x;

    agg_init<<<(elems + 255) / 256, 256>>>(x, eps, 0);

    for (int l = 0; l < LAYERS; l++) {
        float* hout = (l == LAYERS - 1) ? out : ((l & 1) ? hB : hA);

        prep1<<<NPAD1 + 10, 320>>>(W1 + (size_t)l * EMB2 * EMB, Wb + (size_t)l * EMB * 9);

        edge_msg<<<(Ee + EDGES_PER_BLOCK - 1) / EDGES_PER_BLOCK, 256>>>(hin, ei, ea);

        split_A<0, EMB, KP1><<<(Nn * (KP1 / 4) + 255) / 256, 256>>>(agg);

        gemm_s32<<<dim3(NPAD1 / 128, mtiles), 256, SMEM_BYTES>>>(
            Ahi, Alo, Bhi, Blo, z1, Nn, EMB2, KP1, NCHA);

        prep2<<<NPAD2 + 1, 320>>>(W2 + (size_t)l * EMB * EMB2,
                                  bn1g + (size_t)l * EMB2, bn1b + (size_t)l * EMB2);

        split_A<1, EMB2, KP2><<<(Nn * (KP2 / 4) + 255) / 256, 256>>>(z1);

        gemm_s32<<<dim3(NPAD2 / 128, mtiles), 256, SMEM_BYTES>>>(
            Ahi, Alo, Bhi, Blo, z2, Nn, EMB, KP2, NCHB);

        bn_finalize2<<<1, 320>>>(bng + (size_t)l * EMB, bnb + (size_t)l * EMB);

        bn_apply_agg<<<(elems + 255) / 256, 256>>>(z2, hout, eps,
                                                   (l < LAYERS - 1) ? l + 1 : 0,
                                                   (l < LAYERS - 1) ? 1 : 0,
                                                   (l < LAYERS - 1) ? 1 : 0);
        hin = hout;
    }
}